// round 4
// baseline (speedup 1.0000x reference)
#include <cuda_runtime.h>
#include <math.h>

#define B_SZ 512
#define T_SZ 512
#define IN_SZ 128
#define H_SZ 256
#define NB   128   // persistent blocks (<= 148 SMs: single wave, barrier-safe)

// ---------------- scratch (static device globals; no allocation) ----------------
__device__ float g_h0[2][B_SZ * H_SZ];
__device__ float g_h1[2][B_SZ * H_SZ];
__device__ float g_o0[B_SZ * 256];
__device__ float g_o1[B_SZ * 256];
__device__ float g_z [B_SZ * 64];

// grid barrier state (monotonic across replays; zero-initialized at load)
__device__ unsigned g_bar_count;
__device__ volatile unsigned g_bar_phase;

__device__ __forceinline__ float sigmoidf_(float x) { return 1.f / (1.f + expf(-x)); }

// Monotonic sense-reversing grid barrier. Barrier #n releases when the global
// arrive counter reaches 128*n — no counter reset, so no reset race, and state
// is consistent across graph replays (phase is re-read at kernel entry).
__device__ __forceinline__ void grid_bar(unsigned& phase) {
    __syncthreads();
    if (threadIdx.x == 0) {
        __threadfence();
        unsigned prev = phase;
        if (atomicAdd(&g_bar_count, 1u) == prev * (unsigned)NB + (NB - 1)) {
            __threadfence();
            g_bar_phase = prev + 1u;
        } else {
            while (g_bar_phase == prev) { __nanosleep(64); }
        }
        __threadfence();
    }
    __syncthreads();
    phase += 1u;
}

// ---------------- one GEMM phase of a GRU layer, double-buffered staging -------
// W: (768, K) row-major gate-major weights; X: SMEM tile (16, K).
// Each thread: 1 output unit (u_local) x 4 batch rows; 3 gate accumulators each.
template<int K>
__device__ __forceinline__ void phase_mm(
    const float* __restrict__ W, const float* __restrict__ X, float* ws,
    int tid, int us, int u_local, int bgrp,
    float* a0, float* a1, float* a2)
{
    float4 v[6];
    // prefetch chunk 0
    #pragma unroll
    for (int j = 0; j < 6; j++) {
        int idx = tid + j * 256;
        int c4 = idx & 7, row = idx >> 3;
        int g = row >> 6, uu = row & 63;
        v[j] = *(const float4*)(W + (long)(g * 256 + us * 64 + uu) * K + c4 * 4);
    }
    #pragma unroll
    for (int j = 0; j < 6; j++) {
        int idx = tid + j * 256;
        int c4 = idx & 7, row = idx >> 3;
        int g = row >> 6, uu = row & 63;
        *(float4*)(ws + (g * 64 + uu) * 36 + c4 * 4) = v[j];
    }
    __syncthreads();

    int cur = 0;
    for (int kc = 0; kc < K; kc += 32) {
        const bool more = (kc + 32 < K);
        if (more) {  // prefetch next chunk from global while computing current
            #pragma unroll
            for (int j = 0; j < 6; j++) {
                int idx = tid + j * 256;
                int c4 = idx & 7, row = idx >> 3;
                int g = row >> 6, uu = row & 63;
                v[j] = *(const float4*)(W + (long)(g * 256 + us * 64 + uu) * K
                                          + kc + 32 + c4 * 4);
            }
        }
        const float* wb = ws + cur * 6912;
        #pragma unroll
        for (int k = 0; k < 32; k += 4) {
            float4 w0 = *(const float4*)(wb + u_local * 36 + k);
            float4 w1 = *(const float4*)(wb + (64 + u_local) * 36 + k);
            float4 w2 = *(const float4*)(wb + (128 + u_local) * 36 + k);
            #pragma unroll
            for (int b = 0; b < 4; b++) {
                const float4 xv = *(const float4*)(X + (bgrp * 4 + b) * K + kc + k);
                a0[b] += xv.x * w0.x + xv.y * w0.y + xv.z * w0.z + xv.w * w0.w;
                a1[b] += xv.x * w1.x + xv.y * w1.y + xv.z * w1.z + xv.w * w1.w;
                a2[b] += xv.x * w2.x + xv.y * w2.y + xv.z * w2.z + xv.w * w2.w;
            }
        }
        if (more) {
            float* wn = ws + (cur ^ 1) * 6912;
            #pragma unroll
            for (int j = 0; j < 6; j++) {
                int idx = tid + j * 256;
                int c4 = idx & 7, row = idx >> 3;
                int g = row >> 6, uu = row & 63;
                *(float4*)(wn + (g * 64 + uu) * 36 + c4 * 4) = v[j];
            }
            __syncthreads();
            cur ^= 1;
        }
    }
}

// ---------------- one GRU layer for one timestep ----------------
template<int K1>
__device__ void gru_layer(
    const float* __restrict__ in, long in_stride,
    const float* __restrict__ Wih, const float* __restrict__ Whh,
    float br, float bz, float bn, float bh,
    const float* __restrict__ h_in, float* __restrict__ h_out,
    float* xs, float* hs, float* ws,
    int tid, int us, int u_local, int u, int bgrp, int b0)
{
    // input tile (16 x K1)
    for (int i = tid; i < 16 * K1 / 4; i += 256) {
        int bb = i / (K1 / 4), k4 = i % (K1 / 4);
        ((float4*)xs)[i] = *(const float4*)(in + (long)(b0 + bb) * in_stride + k4 * 4);
    }
    // hidden tile (16 x 256)
    for (int i = tid; i < 1024; i += 256) {
        int bb = i >> 6, k4 = i & 63;
        ((float4*)hs)[i] = *(const float4*)(h_in + (b0 + bb) * 256 + k4 * 4);
    }

    float ar[4], az[4], an[4], ah[4];
    #pragma unroll
    for (int b = 0; b < 4; b++) { ar[b] = br; az[b] = bz; an[b] = bn; ah[b] = bh; }

    phase_mm<K1 >(Wih, xs, ws, tid, us, u_local, bgrp, ar, az, an);
    phase_mm<256>(Whh, hs, ws, tid, us, u_local, bgrp, ar, az, ah);

    #pragma unroll
    for (int b = 0; b < 4; b++) {
        int bb = bgrp * 4 + b;
        float r  = sigmoidf_(ar[b]);
        float z  = sigmoidf_(az[b]);
        float n  = tanhf(an[b] + r * ah[b]);
        float hp = hs[bb * 256 + u];
        h_out[(long)(b0 + bb) * 256 + u] = (1.f - z) * n + z * hp;
    }
}

// ---------------- persistent GRU scan: both layers, all 512 steps ----------------
__global__ void __launch_bounds__(256) gru_persistent(
    const float* __restrict__ x,
    const float* __restrict__ W0i, const float* __restrict__ W0h,
    const float* __restrict__ b0i, const float* __restrict__ b0h,
    const float* __restrict__ W1i, const float* __restrict__ W1h,
    const float* __restrict__ b1i, const float* __restrict__ b1h)
{
    extern __shared__ float sm[];
    float* xs = sm;            // 16*256
    float* hs = sm + 4096;     // 16*256
    float* ws = sm + 8192;     // 2 * 3*64*36

    const int tid     = threadIdx.x;
    const int bg      = blockIdx.x >> 2;
    const int us      = blockIdx.x & 3;
    const int u_local = tid & 63;
    const int u       = us * 64 + u_local;
    const int bgrp    = tid >> 6;
    const int b0      = bg * 16;

    __shared__ unsigned s_ph;
    if (tid == 0) s_ph = g_bar_phase;

    // zero initial hidden states (buffer 0): 4 floats per thread per array
    {
        int base = blockIdx.x * 1024 + tid * 4;
        float4 z = make_float4(0.f, 0.f, 0.f, 0.f);
        *(float4*)&g_h0[0][base] = z;
        *(float4*)&g_h1[0][base] = z;
    }
    __syncthreads();
    unsigned phase = s_ph;
    grid_bar(phase);  // zeros visible grid-wide

    // per-layer bias terms (constant over steps)
    const float br0 = b0i[u]       + b0h[u];
    const float bz0 = b0i[256 + u] + b0h[256 + u];
    const float bn0 = b0i[512 + u];
    const float bh0 = b0h[512 + u];
    const float br1 = b1i[u]       + b1h[u];
    const float bz1 = b1i[256 + u] + b1h[256 + u];
    const float bn1 = b1i[512 + u];
    const float bh1 = b1h[512 + u];

    const long HB = (long)B_SZ * H_SZ;
    for (int t = 0; t < T_SZ; t++) {
        const int r = t & 1, w = r ^ 1;
        gru_layer<128>(x + (long)t * IN_SZ, (long)T_SZ * IN_SZ,
                       W0i, W0h, br0, bz0, bn0, bh0,
                       &g_h0[0][0] + r * HB, &g_h0[0][0] + w * HB,
                       xs, hs, ws, tid, us, u_local, u, bgrp, b0);
        grid_bar(phase);
        gru_layer<256>(&g_h0[0][0] + w * HB, 256L,
                       W1i, W1h, br1, bz1, bn1, bh1,
                       &g_h1[0][0] + r * HB, &g_h1[0][0] + w * HB,
                       xs, hs, ws, tid, us, u_local, u, bgrp, b0);
        grid_bar(phase);
    }
    // final h1 (t=511 odd -> w=0) lives in g_h1[0]
}

// ---------------- single-step LSTM pair (h0 = c0 = 0, f-gate dead) ----------
__global__ void __launch_bounds__(128) lstm_head_kernel(
    const float* __restrict__ s,
    const float* __restrict__ Wf, const float* __restrict__ bif, const float* __restrict__ bhf,
    const float* __restrict__ Wr, const float* __restrict__ bir, const float* __restrict__ bhr,
    float* __restrict__ out)
{
    __shared__ float ss[256];
    const int b = blockIdx.x, j = threadIdx.x;
    for (int i = j; i < 256; i += 128) ss[i] = s[b * 256 + i];
    __syncthreads();

    #pragma unroll
    for (int head = 0; head < 2; head++) {
        const float* W  = head ? Wr  : Wf;
        const float* bi = head ? bir : bif;
        const float* bh = head ? bhr : bhf;
        float di  = bi[j]       + bh[j];
        float dg  = bi[256 + j] + bh[256 + j];
        float doo = bi[384 + j] + bh[384 + j];
        const float* Wi = W + (long)j * 256;
        const float* Wg = W + (long)(256 + j) * 256;
        const float* Wo = W + (long)(384 + j) * 256;
        for (int k = 0; k < 256; k += 4) {
            float4 sv = *(const float4*)&ss[k];
            float4 wi = *(const float4*)(Wi + k);
            float4 wg = *(const float4*)(Wg + k);
            float4 wo = *(const float4*)(Wo + k);
            di  += sv.x * wi.x + sv.y * wi.y + sv.z * wi.z + sv.w * wi.w;
            dg  += sv.x * wg.x + sv.y * wg.y + sv.z * wg.z + sv.w * wg.w;
            doo += sv.x * wo.x + sv.y * wo.y + sv.z * wo.z + sv.w * wo.w;
        }
        float c = sigmoidf_(di) * tanhf(dg);
        out[b * 256 + head * 128 + j] = sigmoidf_(doo) * tanhf(c);
    }
}

// ---------------- KAN: cubic B-spline basis (GRID=5, ORDER=3 -> 8 bases) ----------
__device__ __forceinline__ void bspl8(float x, float* bv) {
    const float h = 0.4f;
    float p[12];
    #pragma unroll
    for (int m = 0; m < 12; m++) p[m] = (float)(m - 3) * h - 1.0f;
    float b[11];
    #pragma unroll
    for (int j = 0; j < 11; j++) b[j] = (x >= p[j] && x < p[j + 1]) ? 1.f : 0.f;
    #pragma unroll
    for (int k = 1; k <= 3; k++) {
        #pragma unroll
        for (int j = 0; j < 11 - k; j++) {
            b[j] = (x - p[j]) / (p[j + k] - p[j]) * b[j]
                 + (p[j + k + 1] - x) / (p[j + k + 1] - p[j + 1]) * b[j + 1];
        }
    }
    #pragma unroll
    for (int j = 0; j < 8; j++) bv[j] = b[j];
}

template<int NIN, int NOUT, int NT>
__global__ void __launch_bounds__(NT) kan_kernel(
    const float* __restrict__ in,
    const float* __restrict__ base_w,
    const float* __restrict__ spline_w,
    const float* __restrict__ scaler,
    float* __restrict__ out)
{
    __shared__ float silu_s[NIN];
    __shared__ float bsp_s[NIN][8];
    const int b = blockIdx.x;
    for (int i = threadIdx.x; i < NIN; i += NT) {
        float x = in[b * NIN + i];
        silu_s[i] = x * (1.f / (1.f + expf(-x)));
        bspl8(x, &bsp_s[i][0]);
    }
    __syncthreads();
    for (int o = threadIdx.x; o < NOUT; o += NT) {
        float acc = 0.f;
        for (int i = 0; i < NIN; i++) {
            acc += silu_s[i] * base_w[o * NIN + i];
            const float* sp = spline_w + ((long)o * NIN + i) * 8;
            float s8 = 0.f;
            #pragma unroll
            for (int k = 0; k < 8; k++) s8 += bsp_s[i][k] * sp[k];
            acc += scaler[o * NIN + i] * s8;
        }
        out[b * NOUT + o] = acc;
    }
}

// ---------------- launch ----------------
extern "C" void kernel_launch(void* const* d_in, const int* in_sizes, int n_in,
                              void* d_out, int out_size) {
    const float* x        = (const float*)d_in[0];
    const float* g0_wih   = (const float*)d_in[1];
    const float* g0_whh   = (const float*)d_in[2];
    const float* g0_bih   = (const float*)d_in[3];
    const float* g0_bhh   = (const float*)d_in[4];
    const float* g1_wih   = (const float*)d_in[5];
    const float* g1_whh   = (const float*)d_in[6];
    const float* g1_bih   = (const float*)d_in[7];
    const float* g1_bhh   = (const float*)d_in[8];
    const float* lw_ih0   = (const float*)d_in[9];
    const float* lb_ih0   = (const float*)d_in[11];
    const float* lb_hh0   = (const float*)d_in[12];
    const float* lw_ih0r  = (const float*)d_in[13];
    const float* lb_ih0r  = (const float*)d_in[15];
    const float* lb_hh0r  = (const float*)d_in[16];
    const float* lw_ih1   = (const float*)d_in[17];
    const float* lb_ih1   = (const float*)d_in[19];
    const float* lb_hh1   = (const float*)d_in[20];
    const float* lw_ih1r  = (const float*)d_in[21];
    const float* lb_ih1r  = (const float*)d_in[23];
    const float* lb_hh1r  = (const float*)d_in[24];
    const float* kan1_base   = (const float*)d_in[25];
    const float* kan1_spline = (const float*)d_in[26];
    const float* kan1_scaler = (const float*)d_in[27];
    const float* kan2_base   = (const float*)d_in[28];
    const float* kan2_spline = (const float*)d_in[29];
    const float* kan2_scaler = (const float*)d_in[30];

    float *h1, *o0, *o1, *zz;
    cudaGetSymbolAddress((void**)&h1, g_h1);
    cudaGetSymbolAddress((void**)&o0, g_o0);
    cudaGetSymbolAddress((void**)&o1, g_o1);
    cudaGetSymbolAddress((void**)&zz, g_z);

    const int smem = (4096 + 4096 + 2 * 6912) * 4;  // 88064 B
    cudaFuncSetAttribute(gru_persistent, cudaFuncAttributeMaxDynamicSharedMemorySize, smem);

    gru_persistent<<<NB, 256, smem>>>(x,
                                      g0_wih, g0_whh, g0_bih, g0_bhh,
                                      g1_wih, g1_whh, g1_bih, g1_bhh);

    lstm_head_kernel<<<512, 128>>>(h1, lw_ih0, lb_ih0, lb_hh0,
                                   lw_ih0r, lb_ih0r, lb_hh0r, o0);
    lstm_head_kernel<<<512, 128>>>(o0, lw_ih1, lb_ih1, lb_hh1,
                                   lw_ih1r, lb_ih1r, lb_hh1r, o1);
    kan_kernel<256, 64, 64><<<512, 64>>>(o1, kan1_base, kan1_spline, kan1_scaler, zz);
    kan_kernel<64, 10, 32><<<512, 32>>>(zz, kan2_base, kan2_spline, kan2_scaler, (float*)d_out);
}

// round 5
// speedup vs baseline: 1.2239x; 1.2239x over previous
#include <cuda_runtime.h>
#include <math.h>

#define B_SZ 512
#define T_SZ 512
#define IN_SZ 128
#define H_SZ 256
#define NB   128   // persistent blocks (<= 148 SMs: single wave, barrier-safe)

// ---------------- scratch (static device globals; no allocation) ----------------
__device__ float g_h0[2][B_SZ * H_SZ];
__device__ float g_h1[2][B_SZ * H_SZ];
__device__ float g_o0[B_SZ * 256];
__device__ float g_o1[B_SZ * 256];
__device__ float g_z [B_SZ * 64];

// grid barrier state (monotonic across replays; zero-initialized at load)
__device__ unsigned g_bar_count;
__device__ volatile unsigned g_bar_phase;

__device__ __forceinline__ float sigmoidf_(float x) { return 1.f / (1.f + expf(-x)); }

// packed f32x2 helpers (sm_103a: FFMA2 = full-rate fp32, PTX-only)
__device__ __forceinline__ unsigned long long pack2(float lo, float hi) {
    unsigned long long r;
    asm("mov.b64 %0, {%1, %2};" : "=l"(r) : "f"(lo), "f"(hi));
    return r;
}
__device__ __forceinline__ float2 unpack2(unsigned long long p) {
    float2 v;
    asm("mov.b64 {%0, %1}, %2;" : "=f"(v.x), "=f"(v.y) : "l"(p));
    return v;
}
#define FMA2(acc, a, b) asm("fma.rn.f32x2 %0, %1, %2, %0;" : "+l"(acc) : "l"(a), "l"(b))

// Monotonic sense-reversing grid barrier (no counter reset -> no reset race).
__device__ __forceinline__ void grid_bar(unsigned& phase) {
    __syncthreads();
    if (threadIdx.x == 0) {
        __threadfence();
        unsigned prev = phase;
        if (atomicAdd(&g_bar_count, 1u) == prev * (unsigned)NB + (NB - 1)) {
            __threadfence();
            g_bar_phase = prev + 1u;
        } else {
            while (g_bar_phase == prev) { __nanosleep(64); }
        }
        __threadfence();
    }
    __syncthreads();
    phase += 1u;
}

// ---------------- one GEMM phase of a GRU layer, f32x2 K-packed -----------------
// W: (768, K) gate-major; X: SMEM tile (32, K) row-major.
// Geometry: 8 unit-slices x 32 units; thread = (u_local = tid&31, bgrp = tid>>5).
// Accumulators are f32x2: .lo = even-k partial, .hi = odd-k partial.
// ws buffer: 96 rows (3 gates x 32 units) x 36 floats (32 k + pad), double-buffered.
template<int K>
__device__ __forceinline__ void phase_mm(
    const float* __restrict__ W, const float* __restrict__ X, float* ws,
    int tid, int us, int u_local, int bgrp,
    unsigned long long* a0, unsigned long long* a1, unsigned long long* a2)
{
    float4 v[3];
    // prefetch + store chunk 0
    #pragma unroll
    for (int j = 0; j < 3; j++) {
        int idx = tid + j * 256;
        int c4 = idx & 7, row = idx >> 3;          // row 0..95
        int g = row >> 5, uu = row & 31;
        v[j] = *(const float4*)(W + (long)(g * 256 + us * 32 + uu) * K + c4 * 4);
    }
    #pragma unroll
    for (int j = 0; j < 3; j++) {
        int idx = tid + j * 256;
        int c4 = idx & 7, row = idx >> 3;
        *(float4*)(ws + row * 36 + c4 * 4) = v[j];
    }
    __syncthreads();

    int cur = 0;
    for (int kc = 0; kc < K; kc += 32) {
        const bool more = (kc + 32 < K);
        if (more) {  // prefetch next chunk while computing current
            #pragma unroll
            for (int j = 0; j < 3; j++) {
                int idx = tid + j * 256;
                int c4 = idx & 7, row = idx >> 3;
                int g = row >> 5, uu = row & 31;
                v[j] = *(const float4*)(W + (long)(g * 256 + us * 32 + uu) * K
                                          + kc + 32 + c4 * 4);
            }
        }
        const float* wb = ws + cur * 3456;
        #pragma unroll
        for (int k = 0; k < 32; k += 4) {
            // 4 consecutive k of each gate row = 2 f32x2 pairs
            const ulonglong2 w0 = *(const ulonglong2*)(wb + u_local * 36 + k);
            const ulonglong2 w1 = *(const ulonglong2*)(wb + u_local * 36 + 1152 + k);
            const ulonglong2 w2 = *(const ulonglong2*)(wb + u_local * 36 + 2304 + k);
            #pragma unroll
            for (int b = 0; b < 4; b++) {
                const ulonglong2 xv =
                    *(const ulonglong2*)(X + (bgrp * 4 + b) * K + kc + k);
                FMA2(a0[b], xv.x, w0.x); FMA2(a0[b], xv.y, w0.y);
                FMA2(a1[b], xv.x, w1.x); FMA2(a1[b], xv.y, w1.y);
                FMA2(a2[b], xv.x, w2.x); FMA2(a2[b], xv.y, w2.y);
            }
        }
        if (more) {
            float* wn = ws + (cur ^ 1) * 3456;
            #pragma unroll
            for (int j = 0; j < 3; j++) {
                int idx = tid + j * 256;
                int c4 = idx & 7, row = idx >> 3;
                *(float4*)(wn + row * 36 + c4 * 4) = v[j];
            }
            __syncthreads();
            cur ^= 1;
        }
    }
}

// ---------------- one GRU layer for one timestep ----------------
template<int K1>
__device__ void gru_layer(
    const float* __restrict__ in, long in_stride,
    const float* __restrict__ Wih, const float* __restrict__ Whh,
    float br, float bz, float bn, float bh,
    const float* __restrict__ h_in, float* __restrict__ h_out,
    float* xs, float* hs, float* ws,
    int tid, int us, int u_local, int u, int bgrp, int b0)
{
    // input tile (32 x K1) row-major
    for (int i = tid; i < 32 * K1 / 4; i += 256) {
        int bb = i / (K1 / 4), k4 = i % (K1 / 4);
        ((float4*)xs)[i] = *(const float4*)(in + (long)(b0 + bb) * in_stride + k4 * 4);
    }
    // hidden tile (32 x 256)
    for (int i = tid; i < 2048; i += 256) {
        int bb = i >> 6, k4 = i & 63;
        ((float4*)hs)[i] = *(const float4*)(h_in + (b0 + bb) * 256 + k4 * 4);
    }

    unsigned long long ar[4], az[4], a3[4], ah[4];
    #pragma unroll
    for (int b = 0; b < 4; b++) {
        ar[b] = pack2(br, 0.f); az[b] = pack2(bz, 0.f);
        a3[b] = pack2(bn, 0.f); ah[b] = pack2(bh, 0.f);
    }

    phase_mm<K1 >(Wih, xs, ws, tid, us, u_local, bgrp, ar, az, a3);
    phase_mm<256>(Whh, hs, ws, tid, us, u_local, bgrp, ar, az, ah);

    #pragma unroll
    for (int b = 0; b < 4; b++) {
        int bb = bgrp * 4 + b;
        float2 vr = unpack2(ar[b]);
        float2 vz = unpack2(az[b]);
        float2 vn = unpack2(a3[b]);
        float2 vh = unpack2(ah[b]);
        float r  = sigmoidf_(vr.x + vr.y);
        float z  = sigmoidf_(vz.x + vz.y);
        float n  = tanhf((vn.x + vn.y) + r * (vh.x + vh.y));
        float hp = hs[bb * 256 + u];
        h_out[(long)(b0 + bb) * 256 + u] = (1.f - z) * n + z * hp;
    }
}

// ---------------- persistent GRU scan: both layers, all 512 steps ----------------
__global__ void __launch_bounds__(256) gru_persistent(
    const float* __restrict__ x,
    const float* __restrict__ W0i, const float* __restrict__ W0h,
    const float* __restrict__ b0i, const float* __restrict__ b0h,
    const float* __restrict__ W1i, const float* __restrict__ W1h,
    const float* __restrict__ b1i, const float* __restrict__ b1h)
{
    extern __shared__ float sm[];
    float* xs = sm;            // 32*256
    float* hs = sm + 8192;     // 32*256
    float* ws = sm + 16384;    // 2 * 96*36

    const int tid     = threadIdx.x;
    const int bg      = blockIdx.x >> 3;   // 16 batch-groups
    const int us      = blockIdx.x & 7;    // 8 unit-slices x 32 units
    const int u_local = tid & 31;
    const int u       = us * 32 + u_local;
    const int bgrp    = tid >> 5;          // 8 groups x 4 batch = 32 batch
    const int b0      = bg * 32;

    __shared__ unsigned s_ph;
    if (tid == 0) s_ph = g_bar_phase;

    // zero initial hidden states (buffer 0)
    {
        int base = blockIdx.x * 1024 + tid * 4;
        float4 z = make_float4(0.f, 0.f, 0.f, 0.f);
        *(float4*)&g_h0[0][base] = z;
        *(float4*)&g_h1[0][base] = z;
    }
    __syncthreads();
    unsigned phase = s_ph;
    grid_bar(phase);  // zeros visible grid-wide

    const float br0 = b0i[u]       + b0h[u];
    const float bz0 = b0i[256 + u] + b0h[256 + u];
    const float bn0 = b0i[512 + u];
    const float bh0 = b0h[512 + u];
    const float br1 = b1i[u]       + b1h[u];
    const float bz1 = b1i[256 + u] + b1h[256 + u];
    const float bn1 = b1i[512 + u];
    const float bh1 = b1h[512 + u];

    const long HB = (long)B_SZ * H_SZ;
    for (int t = 0; t < T_SZ; t++) {
        const int r = t & 1, w = r ^ 1;
        gru_layer<128>(x + (long)t * IN_SZ, (long)T_SZ * IN_SZ,
                       W0i, W0h, br0, bz0, bn0, bh0,
                       &g_h0[0][0] + r * HB, &g_h0[0][0] + w * HB,
                       xs, hs, ws, tid, us, u_local, u, bgrp, b0);
        grid_bar(phase);
        gru_layer<256>(&g_h0[0][0] + w * HB, 256L,
                       W1i, W1h, br1, bz1, bn1, bh1,
                       &g_h1[0][0] + r * HB, &g_h1[0][0] + w * HB,
                       xs, hs, ws, tid, us, u_local, u, bgrp, b0);
        grid_bar(phase);
    }
    // final h1 (t=511 odd -> w=0) lives in g_h1[0]
}

// ---------------- single-step LSTM pair (h0 = c0 = 0, f-gate dead) ----------
__global__ void __launch_bounds__(128) lstm_head_kernel(
    const float* __restrict__ s,
    const float* __restrict__ Wf, const float* __restrict__ bif, const float* __restrict__ bhf,
    const float* __restrict__ Wr, const float* __restrict__ bir, const float* __restrict__ bhr,
    float* __restrict__ out)
{
    __shared__ float ss[256];
    const int b = blockIdx.x, j = threadIdx.x;
    for (int i = j; i < 256; i += 128) ss[i] = s[b * 256 + i];
    __syncthreads();

    #pragma unroll
    for (int head = 0; head < 2; head++) {
        const float* W  = head ? Wr  : Wf;
        const float* bi = head ? bir : bif;
        const float* bh = head ? bhr : bhf;
        float di  = bi[j]       + bh[j];
        float dg  = bi[256 + j] + bh[256 + j];
        float doo = bi[384 + j] + bh[384 + j];
        const float* Wi = W + (long)j * 256;
        const float* Wg = W + (long)(256 + j) * 256;
        const float* Wo = W + (long)(384 + j) * 256;
        for (int k = 0; k < 256; k += 4) {
            float4 sv = *(const float4*)&ss[k];
            float4 wi = *(const float4*)(Wi + k);
            float4 wg = *(const float4*)(Wg + k);
            float4 wo = *(const float4*)(Wo + k);
            di  += sv.x * wi.x + sv.y * wi.y + sv.z * wi.z + sv.w * wi.w;
            dg  += sv.x * wg.x + sv.y * wg.y + sv.z * wg.z + sv.w * wg.w;
            doo += sv.x * wo.x + sv.y * wo.y + sv.z * wo.z + sv.w * wo.w;
        }
        float c = sigmoidf_(di) * tanhf(dg);
        out[b * 256 + head * 128 + j] = sigmoidf_(doo) * tanhf(c);
    }
}

// ---------------- KAN: cubic B-spline basis (GRID=5, ORDER=3 -> 8 bases) ----------
__device__ __forceinline__ void bspl8(float x, float* bv) {
    const float h = 0.4f;
    float p[12];
    #pragma unroll
    for (int m = 0; m < 12; m++) p[m] = (float)(m - 3) * h - 1.0f;
    float b[11];
    #pragma unroll
    for (int j = 0; j < 11; j++) b[j] = (x >= p[j] && x < p[j + 1]) ? 1.f : 0.f;
    #pragma unroll
    for (int k = 1; k <= 3; k++) {
        #pragma unroll
        for (int j = 0; j < 11 - k; j++) {
            b[j] = (x - p[j]) / (p[j + k] - p[j]) * b[j]
                 + (p[j + k + 1] - x) / (p[j + k + 1] - p[j + 1]) * b[j + 1];
        }
    }
    #pragma unroll
    for (int j = 0; j < 8; j++) bv[j] = b[j];
}

// kan1: NIN=256, NOUT=64. 256 threads = 64 outputs x 4 input-slices + SMEM reduce.
__global__ void __launch_bounds__(256) kan1_kernel(
    const float* __restrict__ in,
    const float* __restrict__ base_w,
    const float* __restrict__ spline_w,
    const float* __restrict__ scaler,
    float* __restrict__ out)
{
    __shared__ float silu_s[256];
    __shared__ float bsp_s[256][8];
    __shared__ float part[4][64];
    const int b = blockIdx.x, tid = threadIdx.x;
    {
        float xv = in[b * 256 + tid];
        silu_s[tid] = xv / (1.f + expf(-xv));
        bspl8(xv, &bsp_s[tid][0]);
    }
    __syncthreads();
    const int o = tid & 63, s = tid >> 6;
    float acc = 0.f;
    for (int i = s * 64; i < s * 64 + 64; i++) {
        acc += silu_s[i] * base_w[o * 256 + i];
        const float* sp = spline_w + ((long)o * 256 + i) * 8;
        float s8 = 0.f;
        #pragma unroll
        for (int k = 0; k < 8; k++) s8 += bsp_s[i][k] * sp[k];
        acc += scaler[o * 256 + i] * s8;
    }
    part[s][o] = acc;
    __syncthreads();
    if (s == 0) out[b * 64 + o] = part[0][o] + part[1][o] + part[2][o] + part[3][o];
}

// kan2: NIN=64, NOUT=10 (tiny)
__global__ void __launch_bounds__(64) kan2_kernel(
    const float* __restrict__ in,
    const float* __restrict__ base_w,
    const float* __restrict__ spline_w,
    const float* __restrict__ scaler,
    float* __restrict__ out)
{
    __shared__ float silu_s[64];
    __shared__ float bsp_s[64][8];
    const int b = blockIdx.x, tid = threadIdx.x;
    {
        float xv = in[b * 64 + tid];
        silu_s[tid] = xv / (1.f + expf(-xv));
        bspl8(xv, &bsp_s[tid][0]);
    }
    __syncthreads();
    if (tid < 10) {
        float acc = 0.f;
        for (int i = 0; i < 64; i++) {
            acc += silu_s[i] * base_w[tid * 64 + i];
            const float* sp = spline_w + ((long)tid * 64 + i) * 8;
            float s8 = 0.f;
            #pragma unroll
            for (int k = 0; k < 8; k++) s8 += bsp_s[i][k] * sp[k];
            acc += scaler[tid * 64 + i] * s8;
        }
        out[b * 10 + tid] = acc;
    }
}

// ---------------- launch ----------------
extern "C" void kernel_launch(void* const* d_in, const int* in_sizes, int n_in,
                              void* d_out, int out_size) {
    const float* x        = (const float*)d_in[0];
    const float* g0_wih   = (const float*)d_in[1];
    const float* g0_whh   = (const float*)d_in[2];
    const float* g0_bih   = (const float*)d_in[3];
    const float* g0_bhh   = (const float*)d_in[4];
    const float* g1_wih   = (const float*)d_in[5];
    const float* g1_whh   = (const float*)d_in[6];
    const float* g1_bih   = (const float*)d_in[7];
    const float* g1_bhh   = (const float*)d_in[8];
    const float* lw_ih0   = (const float*)d_in[9];
    const float* lb_ih0   = (const float*)d_in[11];
    const float* lb_hh0   = (const float*)d_in[12];
    const float* lw_ih0r  = (const float*)d_in[13];
    const float* lb_ih0r  = (const float*)d_in[15];
    const float* lb_hh0r  = (const float*)d_in[16];
    const float* lw_ih1   = (const float*)d_in[17];
    const float* lb_ih1   = (const float*)d_in[19];
    const float* lb_hh1   = (const float*)d_in[20];
    const float* lw_ih1r  = (const float*)d_in[21];
    const float* lb_ih1r  = (const float*)d_in[23];
    const float* lb_hh1r  = (const float*)d_in[24];
    const float* kan1_base   = (const float*)d_in[25];
    const float* kan1_spline = (const float*)d_in[26];
    const float* kan1_scaler = (const float*)d_in[27];
    const float* kan2_base   = (const float*)d_in[28];
    const float* kan2_spline = (const float*)d_in[29];
    const float* kan2_scaler = (const float*)d_in[30];

    float *h1, *o0, *o1, *zz;
    cudaGetSymbolAddress((void**)&h1, g_h1);
    cudaGetSymbolAddress((void**)&o0, g_o0);
    cudaGetSymbolAddress((void**)&o1, g_o1);
    cudaGetSymbolAddress((void**)&zz, g_z);

    const int smem = (8192 + 8192 + 2 * 3456) * 4;  // 93184 B
    cudaFuncSetAttribute(gru_persistent, cudaFuncAttributeMaxDynamicSharedMemorySize, smem);

    gru_persistent<<<NB, 256, smem>>>(x,
                                      g0_wih, g0_whh, g0_bih, g0_bhh,
                                      g1_wih, g1_whh, g1_bih, g1_bhh);

    lstm_head_kernel<<<512, 128>>>(h1, lw_ih0, lb_ih0, lb_hh0,
                                   lw_ih0r, lb_ih0r, lb_hh0r, o0);
    lstm_head_kernel<<<512, 128>>>(o0, lw_ih1, lb_ih1, lb_hh1,
                                   lw_ih1r, lb_ih1r, lb_hh1r, o1);
    kan1_kernel<<<512, 256>>>(o1, kan1_base, kan1_spline, kan1_scaler, zz);
    kan2_kernel<<<512, 64>>>(zz, kan2_base, kan2_spline, kan2_scaler, (float*)d_out);
}

// round 6
// speedup vs baseline: 1.6778x; 1.3709x over previous
#include <cuda_runtime.h>
#include <math.h>

#define B_SZ 512
#define T_SZ 512
#define IN_SZ 128
#define H_SZ 256
#define NB   128   // 8 batch-groups x 16 unit-slices; <=148 SMs => single wave

typedef unsigned long long ull;

// ---------------- scratch (static device globals; no allocation) ----------------
__device__ float g_h0[2][B_SZ * H_SZ];
__device__ float g_h1[2][B_SZ * H_SZ];
__device__ float g_o0[B_SZ * 256];
__device__ float g_o1[B_SZ * 256];
__device__ float g_z [B_SZ * 64];

// per-group barrier state (8 groups, 128B-padded; monotonic across replays)
__device__ unsigned g_gc[8 * 32];
__device__ volatile unsigned g_gp[8 * 32];

__device__ __forceinline__ float sigmoidf_(float x) { return 1.f / (1.f + expf(-x)); }

// packed f32x2 helpers (sm_103a FFMA2; PTX-only)
__device__ __forceinline__ ull pack2(float lo, float hi) {
    ull r; asm("mov.b64 %0, {%1, %2};" : "=l"(r) : "f"(lo), "f"(hi)); return r;
}
__device__ __forceinline__ float2 unpack2(ull p) {
    float2 v; asm("mov.b64 {%0, %1}, %2;" : "=f"(v.x), "=f"(v.y) : "l"(p)); return v;
}
#define FMA2(acc, a, b) asm("fma.rn.f32x2 %0, %1, %2, %0;" : "+l"(acc) : "l"(a), "l"(b))

// Monotonic group barrier over the 16 blocks sharing bg. __threadfence (gpu scope)
// emits CCTL.IVALL on sm_103a -> reader L1 invalidated, peer h-writes visible.
__device__ __forceinline__ void group_bar(int bg, unsigned& ph) {
    __syncthreads();
    if (threadIdx.x == 0) {
        __threadfence();
        unsigned p = ph;
        if (atomicAdd(&g_gc[bg * 32], 1u) == p * 16u + 15u) {
            __threadfence();
            g_gp[bg * 32] = p + 1u;
        } else {
            while (g_gp[bg * 32] < p + 1u) { __nanosleep(32); }
            __threadfence();
        }
    }
    __syncthreads();
    ph += 1u;
}

// ---- load one weight slice (48 rows = 3 gates x 16 units) into padded SMEM ----
template<int K>
__device__ __forceinline__ void load_w(const float* __restrict__ W, int us,
                                       float* dst, int tid) {
    const int n4 = 48 * K / 4;
    for (int idx = tid; idx < n4; idx += 256) {
        int r = idx / (K / 4), c4 = idx % (K / 4);
        int grow = (r >> 4) * 256 + us * 16 + (r & 15);
        *(float4*)(dst + r * (K + 4) + c4 * 4) =
            *(const float4*)(W + (long)grow * K + c4 * 4);
    }
}

// ---- activation chunk staging: 64 batch x 64 k ----
__device__ __forceinline__ void ld_chunk(float4* v, const float* __restrict__ src,
                                         long rs, int kc, int b0, int tid) {
    #pragma unroll
    for (int j = 0; j < 4; j++) {
        int idx = tid + j * 256;
        int r = idx >> 4, c4 = idx & 15;
        v[j] = *(const float4*)(src + (long)(b0 + r) * rs + kc + c4 * 4);
    }
}
__device__ __forceinline__ void st_chunk(float* dst, const float4* v, int tid) {
    #pragma unroll
    for (int j = 0; j < 4; j++) {
        int idx = tid + j * 256;
        int r = idx >> 4, c4 = idx & 15;
        *(float4*)(dst + r * 64 + c4 * 4) = v[j];
    }
}

// ---- compute one 64-K chunk: 3 gates x 4 batch, f32x2 K-packed accumulators ----
__device__ __forceinline__ void chunk_mm(const float* __restrict__ ws, int WP,
                                         const float* __restrict__ xb,
                                         int u_local, int bgrp,
                                         ull* a0, ull* a1, ull* a2) {
    #pragma unroll
    for (int k = 0; k < 64; k += 4) {
        const ulonglong2 w0 = *(const ulonglong2*)(ws + u_local * WP + k);
        const ulonglong2 w1 = *(const ulonglong2*)(ws + (16 + u_local) * WP + k);
        const ulonglong2 w2 = *(const ulonglong2*)(ws + (32 + u_local) * WP + k);
        #pragma unroll
        for (int b = 0; b < 4; b++) {
            const ulonglong2 xv = *(const ulonglong2*)(xb + (bgrp * 4 + b) * 64 + k);
            FMA2(a0[b], xv.x, w0.x); FMA2(a0[b], xv.y, w0.y);
            FMA2(a1[b], xv.x, w1.x); FMA2(a1[b], xv.y, w1.y);
            FMA2(a2[b], xv.x, w2.x); FMA2(a2[b], xv.y, w2.y);
        }
    }
}

// ---- one GRU layer for one timestep (weights already in SMEM) ----
template<int K1, int WP1>
__device__ void gru_layer(
    const float* __restrict__ in1, long s1,            // ih input (64 x K1)
    const float* __restrict__ h_in,                    // (512,256)
    const float* wih, const float* whh,                // SMEM, padded
    float br, float bz, float bn, float bh,
    float* __restrict__ h_out, float* xbuf,
    int tid, int u_local, int bgrp, int u, int b0)
{
    ull ar[4], az[4], an_[4], ah[4];
    #pragma unroll
    for (int b = 0; b < 4; b++) {
        ar[b] = pack2(br, 0.f); az[b] = pack2(bz, 0.f);
        an_[b] = pack2(bn, 0.f); ah[b] = pack2(bh, 0.f);
    }

    constexpr int NC1 = K1 / 64;
    float4 v[4];
    ld_chunk(v, in1, s1, 0, b0, tid);
    int buf = 0;

    // ih phase
    #pragma unroll 1
    for (int c = 0; c < NC1; c++) {
        st_chunk(xbuf + buf * 4096, v, tid);
        __syncthreads();
        if (c + 1 < NC1) ld_chunk(v, in1, s1, (c + 1) * 64, b0, tid);
        else             ld_chunk(v, h_in, 256, 0, b0, tid);
        chunk_mm(wih + c * 64, WP1, xbuf + buf * 4096, u_local, bgrp, ar, az, an_);
        buf ^= 1;
    }
    // hh phase
    #pragma unroll 1
    for (int c = 0; c < 4; c++) {
        st_chunk(xbuf + buf * 4096, v, tid);
        __syncthreads();
        if (c + 1 < 4) ld_chunk(v, h_in, 256, (c + 1) * 64, b0, tid);
        chunk_mm(whh + c * 64, 260, xbuf + buf * 4096, u_local, bgrp, ar, az, ah);
        buf ^= 1;
    }

    #pragma unroll
    for (int b = 0; b < 4; b++) {
        int bb = bgrp * 4 + b;
        float2 vr = unpack2(ar[b]);
        float2 vz = unpack2(az[b]);
        float2 vn = unpack2(an_[b]);
        float2 vh = unpack2(ah[b]);
        float r  = sigmoidf_(vr.x + vr.y);
        float z  = sigmoidf_(vz.x + vz.y);
        float n  = tanhf((vn.x + vn.y) + r * (vh.x + vh.y));
        float hp = h_in[(long)(b0 + bb) * 256 + u];
        h_out[(long)(b0 + bb) * 256 + u] = (1.f - z) * n + z * hp;
    }
}

// ---------------- persistent GRU scan: weights SMEM-resident ----------------
// SMEM floats: w0i 48x132=6336 | w0h 48x260=12480 | w1i 12480 | w1h 12480 | xbuf 2x4096
__global__ void __launch_bounds__(256) gru_persistent(
    const float* __restrict__ x,
    const float* __restrict__ W0i, const float* __restrict__ W0h,
    const float* __restrict__ b0i, const float* __restrict__ b0h,
    const float* __restrict__ W1i, const float* __restrict__ W1h,
    const float* __restrict__ b1i, const float* __restrict__ b1h)
{
    extern __shared__ float sm[];
    float* w0i = sm;
    float* w0h = sm + 6336;
    float* w1i = sm + 18816;
    float* w1h = sm + 31296;
    float* xbuf = sm + 43776;

    const int tid     = threadIdx.x;
    const int bg      = blockIdx.x >> 4;   // 8 groups of 64 batch
    const int us      = blockIdx.x & 15;   // 16 unit-slices of 16 units
    const int u_local = tid & 15;
    const int u       = us * 16 + u_local;
    const int bgrp    = tid >> 4;          // 16 groups x 4 batch
    const int b0      = bg * 64;

    load_w<128>(W0i, us, w0i, tid);
    load_w<256>(W0h, us, w0h, tid);
    load_w<256>(W1i, us, w1i, tid);
    load_w<256>(W1h, us, w1h, tid);

    // zero initial hidden states (buffer 0): this block's share of its bg rows
    {
        int off = bg * 16384 + us * 1024 + tid * 4;
        float4 z = make_float4(0.f, 0.f, 0.f, 0.f);
        *(float4*)&g_h0[0][off] = z;
        *(float4*)&g_h1[0][off] = z;
    }
    unsigned ph = g_gp[bg * 32];
    group_bar(bg, ph);  // zeros visible in group; weights are block-local

    const float br0 = b0i[u]       + b0h[u];
    const float bz0 = b0i[256 + u] + b0h[256 + u];
    const float bn0 = b0i[512 + u];
    const float bh0 = b0h[512 + u];
    const float br1 = b1i[u]       + b1h[u];
    const float bz1 = b1i[256 + u] + b1h[256 + u];
    const float bn1 = b1i[512 + u];
    const float bh1 = b1h[512 + u];

    const long HB = (long)B_SZ * H_SZ;
    for (int t = 0; t < T_SZ; t++) {
        const int r = t & 1, w = r ^ 1;
        gru_layer<128, 132>(x + (long)t * IN_SZ, (long)T_SZ * IN_SZ,
                            &g_h0[0][0] + r * HB,
                            w0i, w0h, br0, bz0, bn0, bh0,
                            &g_h0[0][0] + w * HB, xbuf,
                            tid, u_local, bgrp, u, b0);
        group_bar(bg, ph);   // peers' h0(t) ready; double-buffering covers the rest
        gru_layer<256, 260>(&g_h0[0][0] + w * HB, 256L,
                            &g_h1[0][0] + r * HB,
                            w1i, w1h, br1, bz1, bn1, bh1,
                            &g_h1[0][0] + w * HB, xbuf,
                            tid, u_local, bgrp, u, b0);
    }
    // final h1 (t=511 odd -> w=0) lives in g_h1[0]
}

// ---------- LSTM heads: warp-per-output, lanes split K (coalesced) ----------
__global__ void __launch_bounds__(256) lstm_head_kernel(
    const float* __restrict__ s,
    const float* __restrict__ Wf, const float* __restrict__ bif, const float* __restrict__ bhf,
    const float* __restrict__ Wr, const float* __restrict__ bir, const float* __restrict__ bhr,
    float* __restrict__ out)
{
    __shared__ float ss[256];
    const int b = blockIdx.x, tid = threadIdx.x;
    const int warp = tid >> 5, lane = tid & 31;
    ss[tid] = s[b * 256 + tid];
    __syncthreads();

    #pragma unroll 1
    for (int oo = 0; oo < 32; oo++) {
        int idx = warp * 32 + oo;          // 0..255 = 2 heads x 128 outputs
        int hd = idx >> 7, j = idx & 127;
        const float* W  = hd ? Wr  : Wf;
        const float* bi = hd ? bir : bif;
        const float* bh = hd ? bhr : bhf;
        float di = 0.f, dg = 0.f, doo = 0.f;
        #pragma unroll
        for (int kk = 0; kk < 8; kk++) {
            int k = kk * 32 + lane;
            float sv = ss[k];
            di  += sv * W[(long)j * 256 + k];
            dg  += sv * W[(long)(256 + j) * 256 + k];
            doo += sv * W[(long)(384 + j) * 256 + k];
        }
        #pragma unroll
        for (int off = 16; off; off >>= 1) {
            di  += __shfl_xor_sync(0xffffffffu, di,  off);
            dg  += __shfl_xor_sync(0xffffffffu, dg,  off);
            doo += __shfl_xor_sync(0xffffffffu, doo, off);
        }
        if (lane == 0) {
            di  += bi[j]       + bh[j];
            dg  += bi[256 + j] + bh[256 + j];
            doo += bi[384 + j] + bh[384 + j];
            float c = sigmoidf_(di) * tanhf(dg);
            out[b * 256 + hd * 128 + j] = sigmoidf_(doo) * tanhf(c);
        }
    }
}

// ---------------- KAN: cubic B-spline basis (8 bases) ----------
__device__ __forceinline__ void bspl8(float x, float* bv) {
    const float h = 0.4f;
    float p[12];
    #pragma unroll
    for (int m = 0; m < 12; m++) p[m] = (float)(m - 3) * h - 1.0f;
    float b[11];
    #pragma unroll
    for (int j = 0; j < 11; j++) b[j] = (x >= p[j] && x < p[j + 1]) ? 1.f : 0.f;
    #pragma unroll
    for (int k = 1; k <= 3; k++) {
        #pragma unroll
        for (int j = 0; j < 11 - k; j++) {
            b[j] = (x - p[j]) / (p[j + k] - p[j]) * b[j]
                 + (p[j + k + 1] - x) / (p[j + k + 1] - p[j + 1]) * b[j + 1];
        }
    }
    #pragma unroll
    for (int j = 0; j < 8; j++) bv[j] = b[j];
}

// kan1: warp-per-output, lanes split the 256 inputs (coalesced weight reads)
__global__ void __launch_bounds__(256) kan1_kernel(
    const float* __restrict__ in,
    const float* __restrict__ base_w,
    const float* __restrict__ spline_w,
    const float* __restrict__ scaler,
    float* __restrict__ out)
{
    __shared__ float silu_s[256];
    __shared__ float bsp_s[256][9];   // pad 9: kills 4-way bank conflict
    const int b = blockIdx.x, tid = threadIdx.x;
    const int warp = tid >> 5, lane = tid & 31;
    {
        float xv = in[b * 256 + tid];
        silu_s[tid] = xv / (1.f + expf(-xv));
        float bv[8]; bspl8(xv, bv);
        #pragma unroll
        for (int k = 0; k < 8; k++) bsp_s[tid][k] = bv[k];
    }
    __syncthreads();
    #pragma unroll 1
    for (int o = warp * 8; o < warp * 8 + 8; o++) {
        float acc = 0.f;
        #pragma unroll
        for (int ii = 0; ii < 8; ii++) {
            int i = ii * 32 + lane;
            acc += silu_s[i] * base_w[o * 256 + i];
            const float4* sp = (const float4*)(spline_w + ((long)o * 256 + i) * 8);
            float4 s0 = sp[0], s1 = sp[1];
            float s8 = bsp_s[i][0] * s0.x + bsp_s[i][1] * s0.y
                     + bsp_s[i][2] * s0.z + bsp_s[i][3] * s0.w
                     + bsp_s[i][4] * s1.x + bsp_s[i][5] * s1.y
                     + bsp_s[i][6] * s1.z + bsp_s[i][7] * s1.w;
            acc += scaler[o * 256 + i] * s8;
        }
        #pragma unroll
        for (int off = 16; off; off >>= 1) acc += __shfl_xor_sync(0xffffffffu, acc, off);
        if (lane == 0) out[b * 64 + o] = acc;
    }
}

// kan2: NIN=64, NOUT=10 (tiny)
__global__ void __launch_bounds__(64) kan2_kernel(
    const float* __restrict__ in,
    const float* __restrict__ base_w,
    const float* __restrict__ spline_w,
    const float* __restrict__ scaler,
    float* __restrict__ out)
{
    __shared__ float silu_s[64];
    __shared__ float bsp_s[64][9];
    const int b = blockIdx.x, tid = threadIdx.x;
    {
        float xv = in[b * 64 + tid];
        silu_s[tid] = xv / (1.f + expf(-xv));
        float bv[8]; bspl8(xv, bv);
        #pragma unroll
        for (int k = 0; k < 8; k++) bsp_s[tid][k] = bv[k];
    }
    __syncthreads();
    const int warp = tid >> 5, lane = tid & 31;
    if (warp < 2) {
        #pragma unroll 1
        for (int o = warp * 5; o < warp * 5 + 5; o++) {
            float acc = 0.f;
            #pragma unroll
            for (int ii = 0; ii < 2; ii++) {
                int i = ii * 32 + lane;
                acc += silu_s[i] * base_w[o * 64 + i];
                const float4* sp = (const float4*)(spline_w + ((long)o * 64 + i) * 8);
                float4 s0 = sp[0], s1 = sp[1];
                float s8 = bsp_s[i][0] * s0.x + bsp_s[i][1] * s0.y
                         + bsp_s[i][2] * s0.z + bsp_s[i][3] * s0.w
                         + bsp_s[i][4] * s1.x + bsp_s[i][5] * s1.y
                         + bsp_s[i][6] * s1.z + bsp_s[i][7] * s1.w;
                acc += scaler[o * 64 + i] * s8;
            }
            #pragma unroll
            for (int off = 16; off; off >>= 1) acc += __shfl_xor_sync(0xffffffffu, acc, off);
            if (lane == 0) out[b * 10 + o] = acc;
        }
    }
}

// ---------------- launch ----------------
extern "C" void kernel_launch(void* const* d_in, const int* in_sizes, int n_in,
                              void* d_out, int out_size) {
    const float* x        = (const float*)d_in[0];
    const float* g0_wih   = (const float*)d_in[1];
    const float* g0_whh   = (const float*)d_in[2];
    const float* g0_bih   = (const float*)d_in[3];
    const float* g0_bhh   = (const float*)d_in[4];
    const float* g1_wih   = (const float*)d_in[5];
    const float* g1_whh   = (const float*)d_in[6];
    const float* g1_bih   = (const float*)d_in[7];
    const float* g1_bhh   = (const float*)d_in[8];
    const float* lw_ih0   = (const float*)d_in[9];
    const float* lb_ih0   = (const float*)d_in[11];
    const float* lb_hh0   = (const float*)d_in[12];
    const float* lw_ih0r  = (const float*)d_in[13];
    const float* lb_ih0r  = (const float*)d_in[15];
    const float* lb_hh0r  = (const float*)d_in[16];
    const float* lw_ih1   = (const float*)d_in[17];
    const float* lb_ih1   = (const float*)d_in[19];
    const float* lb_hh1   = (const float*)d_in[20];
    const float* lw_ih1r  = (const float*)d_in[21];
    const float* lb_ih1r  = (const float*)d_in[23];
    const float* lb_hh1r  = (const float*)d_in[24];
    const float* kan1_base   = (const float*)d_in[25];
    const float* kan1_spline = (const float*)d_in[26];
    const float* kan1_scaler = (const float*)d_in[27];
    const float* kan2_base   = (const float*)d_in[28];
    const float* kan2_spline = (const float*)d_in[29];
    const float* kan2_scaler = (const float*)d_in[30];

    float *h1, *o0, *o1, *zz;
    cudaGetSymbolAddress((void**)&h1, g_h1);
    cudaGetSymbolAddress((void**)&o0, g_o0);
    cudaGetSymbolAddress((void**)&o1, g_o1);
    cudaGetSymbolAddress((void**)&zz, g_z);

    const int smem = (6336 + 12480 + 12480 + 12480 + 8192) * 4;  // 207,872 B
    cudaFuncSetAttribute(gru_persistent, cudaFuncAttributeMaxDynamicSharedMemorySize, smem);

    gru_persistent<<<NB, 256, smem>>>(x,
                                      g0_wih, g0_whh, g0_bih, g0_bhh,
                                      g1_wih, g1_whh, g1_bih, g1_bhh);

    lstm_head_kernel<<<512, 256>>>(h1, lw_ih0, lb_ih0, lb_hh0,
                                   lw_ih0r, lb_ih0r, lb_hh0r, o0);
    lstm_head_kernel<<<512, 256>>>(o0, lw_ih1, lb_ih1, lb_hh1,
                                   lw_ih1r, lb_ih1r, lb_hh1r, o1);
    kan1_kernel<<<512, 256>>>(o1, kan1_base, kan1_spline, kan1_scaler, zz);
    kan2_kernel<<<512, 64>>>(zz, kan2_base, kan2_spline, kan2_scaler, (float*)d_out);
}